// round 6
// baseline (speedup 1.0000x reference)
#include <cuda_runtime.h>
#include <cuda_fp16.h>

#define D      128
#define D4     32          // D/4 float4 per row (fp32 views)
#define DH2    32          // D/4 uint2 per row (fp16 views)
#define KHOPS  10

static const int NMAX = 50000;
static const int EMAX = 625000;

// ---------------- scratch (device globals; no allocation allowed) ----------
__device__ __half g_bufA[NMAX * D];     // h ping (fp16 state)
__device__ __half g_bufB[NMAX * D];     // h pong
__device__ int    g_deg[NMAX];
__device__ int    g_rowptr[NMAX + 1];
__device__ int    g_cursor[NMAX];
__device__ float  g_dinv[NMAX];
__device__ int2   g_csr[EMAX];          // {src, bitcast(dinv[src])}
__device__ float  g_Wt[D * D];          // W transposed: Wt[k][o]
__device__ float  g_coeff[KHOPS + 1];
__device__ int    g_is64;

// ---------------- packed f32x2 helpers (Blackwell FFMA2 via PTX) -----------
__device__ __forceinline__ unsigned long long pack2(float v) {
    unsigned long long r;
    asm("mov.b64 %0, {%1, %1};" : "=l"(r) : "f"(v));
    return r;
}
__device__ __forceinline__ unsigned long long ffma2(
    unsigned long long a, unsigned long long b, unsigned long long c) {
    unsigned long long d;
    asm("fma.rn.f32x2 %0, %1, %2, %3;" : "=l"(d) : "l"(a), "l"(b), "l"(c));
    return d;
}
__device__ __forceinline__ float2 unpack2(unsigned long long v) {
    float lo, hi;
    asm("mov.b64 {%0, %1}, %2;" : "=f"(lo), "=f"(hi) : "l"(v));
    return make_float2(lo, hi);
}

// ---------------- fused setup: W transpose + dtype detect + coeffs ----------
__global__ void k_setup(const void* __restrict__ ei,
                        const float* __restrict__ t_ptr,
                        const float* __restrict__ W) {
    int i = blockIdx.x * blockDim.x + threadIdx.x;
    if (i < D * D) {
        int r = i / D, c = i % D;
        g_Wt[c * D + r] = W[r * D + c];
    }
    if (blockIdx.x == 0 && threadIdx.x == 0) {
        const int* a = (const int*)ei;
        int is64 = 1;
#pragma unroll
        for (int j = 1; j < 32; j += 2)
            if (a[j] != 0) is64 = 0;
        g_is64 = is64;
        float t = *t_ptr;
        float cc = expf(-t);
        g_coeff[0] = cc;
        for (int k = 1; k <= KHOPS; ++k) { cc = cc * t / (float)k; g_coeff[k] = cc; }
    }
}

__device__ __forceinline__ int load_idx(const void* ei, long long pos) {
    if (g_is64) return (int)((const long long*)ei)[pos];
    return ((const int*)ei)[pos];
}

__global__ void k_zero(int n) {
    int i = blockIdx.x * blockDim.x + threadIdx.x;
    if (i < n) g_deg[i] = 0;
}

__global__ void k_hist(const void* __restrict__ ei, int E) {
    int e = blockIdx.x * blockDim.x + threadIdx.x;
    if (e < E) {
        int dst = load_idx(ei, (long long)E + e);
        atomicAdd(&g_deg[dst], 1);
    }
}

// Single-block exclusive scan + fused prep (cursor copy, dinv).
__global__ void __launch_bounds__(1024) k_scan(int n) {
    const int T = 1024;
    int tid  = threadIdx.x;
    int per  = (n + T - 1) / T;
    int s    = tid * per;
    int epos = s + per; if (epos > n) epos = n; if (s > n) s = n;

    int sum = 0;
    for (int i = s; i < epos; ++i) sum += g_deg[i];

    int lane = tid & 31, wid = tid >> 5;
    int v = sum;
#pragma unroll
    for (int off = 1; off < 32; off <<= 1) {
        int t = __shfl_up_sync(0xffffffffu, v, off);
        if (lane >= off) v += t;
    }
    __shared__ int wsum[32];
    if (lane == 31) wsum[wid] = v;
    __syncthreads();
    if (wid == 0) {
        int wv = wsum[lane];
#pragma unroll
        for (int off = 1; off < 32; off <<= 1) {
            int t = __shfl_up_sync(0xffffffffu, wv, off);
            if (lane >= off) wv += t;
        }
        wsum[lane] = wv;
    }
    __syncthreads();

    int excl = v - sum + (wid ? wsum[wid - 1] : 0);
    int run = excl;
    for (int i = s; i < epos; ++i) {
        int d = g_deg[i];
        g_rowptr[i] = run;
        g_cursor[i] = run;
        g_dinv[i]   = rsqrtf((float)d + 1.0f);
        run += d;
    }
    if (tid == T - 1) g_rowptr[n] = run;
}

__global__ void k_scatter(const void* __restrict__ ei, int E) {
    int e = blockIdx.x * blockDim.x + threadIdx.x;
    if (e < E) {
        int src = load_idx(ei, e);
        int dst = load_idx(ei, (long long)E + e);
        int pos = atomicAdd(&g_cursor[dst], 1);
        g_csr[pos] = make_int2(src, __float_as_int(g_dinv[src]));
    }
}

// ------------- fp16 pack/unpack helpers -------------------------------------
__device__ __forceinline__ void fma_h4(uint2 p, float w, float4& a) {
    float2 lo = __half22float2(*(const __half2*)&p.x);
    float2 hi = __half22float2(*(const __half2*)&p.y);
    a.x = fmaf(w, lo.x, a.x); a.y = fmaf(w, lo.y, a.y);
    a.z = fmaf(w, hi.x, a.z); a.w = fmaf(w, hi.y, a.w);
}
__device__ __forceinline__ uint2 pack_h4(float4 r) {
    __half2 lo = __floats2half2_rn(r.x, r.y);
    __half2 hi = __floats2half2_rn(r.z, r.w);
    uint2 p;
    p.x = *(const unsigned int*)&lo;
    p.y = *(const unsigned int*)&hi;
    return p;
}

// ---------------- y = x @ W^T ; h0 = fp16(y) ; out = c0*y + b ---------------
// 256 threads = 8 warps; block computes 32 rows.
// x tile staged in smem PRE-DUPLICATED as (x,x) u64 pairs so the packed-f32x2
// inner loop needs zero pack instructions: 8 FFMA2 + 4 broadcast LDS per k.
__global__ void __launch_bounds__(256) k_gemm_init(
    const float* __restrict__ x, const float* __restrict__ b,
    float* __restrict__ out, int n)
{
    __shared__ unsigned long long sdup[32 * D];   // 32 KB
    int tid  = threadIdx.x;
    int warp = tid >> 5;
    int lane = tid & 31;
    int rowb = blockIdx.x * 32;
    int rows = n - rowb; if (rows > 32) rows = 32;

    const float4* x4 = (const float4*)(x + (long long)rowb * D);
    for (int i = tid; i < rows * D4; i += 256) {
        float4 xv = x4[i];
        sdup[i * 4 + 0] = pack2(xv.x);
        sdup[i * 4 + 1] = pack2(xv.y);
        sdup[i * 4 + 2] = pack2(xv.z);
        sdup[i * 4 + 3] = pack2(xv.w);
    }
    __syncthreads();

    int r0 = warp * 4;
    if (rowb + r0 >= n) return;
    int nr = rows - r0; if (nr > 4) nr = 4;   // rows is a multiple of 4 here (N%4==0)

    const ulonglong2* __restrict__ Wt2 = (const ulonglong2*)g_Wt;

    unsigned long long acc[4][2];
#pragma unroll
    for (int r = 0; r < 4; ++r) { acc[r][0] = 0ull; acc[r][1] = 0ull; }

#pragma unroll 4
    for (int kc = 0; kc < D; ++kc) {
        ulonglong2 wp = __ldg(&Wt2[kc * D4 + lane]);   // (w0,w1),(w2,w3) cols
        unsigned long long v0 = sdup[(r0 + 0) * D + kc];
        unsigned long long v1 = sdup[(r0 + 1) * D + kc];
        unsigned long long v2 = sdup[(r0 + 2) * D + kc];
        unsigned long long v3 = sdup[(r0 + 3) * D + kc];
        acc[0][0] = ffma2(v0, wp.x, acc[0][0]); acc[0][1] = ffma2(v0, wp.y, acc[0][1]);
        acc[1][0] = ffma2(v1, wp.x, acc[1][0]); acc[1][1] = ffma2(v1, wp.y, acc[1][1]);
        acc[2][0] = ffma2(v2, wp.x, acc[2][0]); acc[2][1] = ffma2(v2, wp.y, acc[2][1]);
        acc[3][0] = ffma2(v3, wp.x, acc[3][0]); acc[3][1] = ffma2(v3, wp.y, acc[3][1]);
    }

    float c0 = g_coeff[0];
    float4 b4 = __ldg(&((const float4*)b)[lane]);
    uint2*  h0 = (uint2*)g_bufA;
    float4* o4 = (float4*)out;

#pragma unroll
    for (int j = 0; j < 4; ++j) {
        if (j < nr) {
            int idx = (rowb + r0 + j) * D4 + lane;
            float2 lo = unpack2(acc[j][0]);
            float2 hi = unpack2(acc[j][1]);
            float4 r = make_float4(lo.x, lo.y, hi.x, hi.y);
            h0[idx] = pack_h4(r);
            float4 o;
            o.x = fmaf(c0, r.x, b4.x);
            o.y = fmaf(c0, r.y, b4.y);
            o.z = fmaf(c0, r.z, b4.z);
            o.w = fmaf(c0, r.w, b4.w);
            o4[idx] = o;
        }
    }
}

// ---------------- one diffusion hop (fp16 state) -----------------------------
// warp per node: r = dinv[i]*(sum_e w_e*h[src_e]) + dinv[i]^2 * h[i]
// write_h: store hout (skipped on final hop)
// do_out : out += coeff[k-1]*hin_self + coeff[k]*r  (even hops: 2 terms/RMW)
__global__ void __launch_bounds__(256) k_hop(
    int flip, int k, int n, float4* __restrict__ out, int do_out, int write_h)
{
    int gw = (blockIdx.x * blockDim.x + threadIdx.x) >> 5;
    if (gw >= n) return;
    int lane = threadIdx.x & 31;

    const uint2* __restrict__ hin  = flip ? (const uint2*)g_bufB : (const uint2*)g_bufA;
    uint2*       __restrict__ hout = flip ? (uint2*)g_bufA       : (uint2*)g_bufB;

    int beg = g_rowptr[gw];
    int end = g_rowptr[gw + 1];

    uint2 ps = __ldg(&hin[gw * DH2 + lane]);   // self row (hoisted for overlap)

    float4 acc  = make_float4(0.f,0.f,0.f,0.f);
    float4 acc2 = make_float4(0.f,0.f,0.f,0.f);

    int e = beg;
    for (; e + 8 <= end; e += 8) {
        int2 c0 = __ldg(&g_csr[e + 0]);
        int2 c1 = __ldg(&g_csr[e + 1]);
        int2 c2 = __ldg(&g_csr[e + 2]);
        int2 c3 = __ldg(&g_csr[e + 3]);
        int2 c4 = __ldg(&g_csr[e + 4]);
        int2 c5 = __ldg(&g_csr[e + 5]);
        int2 c6 = __ldg(&g_csr[e + 6]);
        int2 c7 = __ldg(&g_csr[e + 7]);
        uint2 p0 = __ldg(&hin[c0.x * DH2 + lane]);
        uint2 p1 = __ldg(&hin[c1.x * DH2 + lane]);
        uint2 p2 = __ldg(&hin[c2.x * DH2 + lane]);
        uint2 p3 = __ldg(&hin[c3.x * DH2 + lane]);
        uint2 p4 = __ldg(&hin[c4.x * DH2 + lane]);
        uint2 p5 = __ldg(&hin[c5.x * DH2 + lane]);
        uint2 p6 = __ldg(&hin[c6.x * DH2 + lane]);
        uint2 p7 = __ldg(&hin[c7.x * DH2 + lane]);
        fma_h4(p0, __int_as_float(c0.y), acc);
        fma_h4(p1, __int_as_float(c1.y), acc2);
        fma_h4(p2, __int_as_float(c2.y), acc);
        fma_h4(p3, __int_as_float(c3.y), acc2);
        fma_h4(p4, __int_as_float(c4.y), acc);
        fma_h4(p5, __int_as_float(c5.y), acc2);
        fma_h4(p6, __int_as_float(c6.y), acc);
        fma_h4(p7, __int_as_float(c7.y), acc2);
    }
    for (; e + 4 <= end; e += 4) {
        int2 c0 = __ldg(&g_csr[e + 0]);
        int2 c1 = __ldg(&g_csr[e + 1]);
        int2 c2 = __ldg(&g_csr[e + 2]);
        int2 c3 = __ldg(&g_csr[e + 3]);
        uint2 p0 = __ldg(&hin[c0.x * DH2 + lane]);
        uint2 p1 = __ldg(&hin[c1.x * DH2 + lane]);
        uint2 p2 = __ldg(&hin[c2.x * DH2 + lane]);
        uint2 p3 = __ldg(&hin[c3.x * DH2 + lane]);
        fma_h4(p0, __int_as_float(c0.y), acc);
        fma_h4(p1, __int_as_float(c1.y), acc2);
        fma_h4(p2, __int_as_float(c2.y), acc);
        fma_h4(p3, __int_as_float(c3.y), acc2);
    }
    for (; e < end; ++e) {
        int2 c = __ldg(&g_csr[e]);
        uint2 p = __ldg(&hin[c.x * DH2 + lane]);
        fma_h4(p, __int_as_float(c.y), acc);
    }

    float di  = g_dinv[gw];
    float di2 = di * di;
    float2 slo = __half22float2(*(const __half2*)&ps.x);
    float2 shi = __half22float2(*(const __half2*)&ps.y);

    float4 r;
    r.x = fmaf(di, acc.x + acc2.x, di2 * slo.x);
    r.y = fmaf(di, acc.y + acc2.y, di2 * slo.y);
    r.z = fmaf(di, acc.z + acc2.z, di2 * shi.x);
    r.w = fmaf(di, acc.w + acc2.w, di2 * shi.y);

    int idx = gw * DH2 + lane;
    if (write_h) hout[idx] = pack_h4(r);

    if (do_out) {
        float cp = g_coeff[k - 1];
        float c  = g_coeff[k];
        float4 o = out[idx];
        o.x = fmaf(cp, slo.x, o.x);
        o.y = fmaf(cp, slo.y, o.y);
        o.z = fmaf(cp, shi.x, o.z);
        o.w = fmaf(cp, shi.y, o.w);
        o.x = fmaf(c, r.x, o.x);
        o.y = fmaf(c, r.y, o.y);
        o.z = fmaf(c, r.z, o.z);
        o.w = fmaf(c, r.w, o.w);
        out[idx] = o;
    }
}

// ---------------- launch ----------------------------------------------------
extern "C" void kernel_launch(void* const* d_in, const int* in_sizes, int n_in,
                              void* d_out, int out_size) {
    const float* x  = (const float*)d_in[0];
    const void*  ei = d_in[1];
    const float* t  = (const float*)d_in[2];
    const float* W  = (const float*)d_in[3];
    const float* b  = (const float*)d_in[4];
    float* out = (float*)d_out;

    int N = in_sizes[0] / D;
    int E = in_sizes[1] / 2;

    k_setup<<<(D * D + 255) / 256, 256>>>(ei, t, W);
    k_zero<<<(N + 255) / 256, 256>>>(N);
    k_hist<<<(E + 255) / 256, 256>>>(ei, E);
    k_scan<<<1, 1024>>>(N);
    k_scatter<<<(E + 255) / 256, 256>>>(ei, E);
    k_gemm_init<<<(N + 31) / 32, 256>>>(x, b, out, N);

    int hop_blocks = (N + 7) / 8;   // 8 warps per block, warp per node
    for (int k = 1; k <= KHOPS; ++k) {
        int flip    = (k - 1) & 1;
        int do_out  = (k & 1) == 0;
        int write_h = (k < KHOPS);
        k_hop<<<hop_blocks, 256>>>(flip, k, N, (float4*)out, do_out, write_h);
    }
}

// round 7
// speedup vs baseline: 1.2808x; 1.2808x over previous
#include <cuda_runtime.h>
#include <cuda_fp16.h>

#define D      128
#define D4     32          // D/4 float4 per row (fp32 views)
#define DH2    32          // D/4 uint2 per row (fp16 views)
#define KHOPS  10
#define SCAN_T 1024

static const int NMAX = 50000;
static const int EMAX = 625000;
static const int BMAX = 64;             // max scan blocks (50000/1024 = 49)

// ---------------- scratch (device globals; no allocation allowed) ----------
__device__ __half g_bufA[NMAX * D];     // h ping (fp16 state)
__device__ __half g_bufB[NMAX * D];     // h pong
__device__ int    g_deg[NMAX];
__device__ int    g_rowptr[NMAX + 1];
__device__ int    g_cursor[NMAX];
__device__ float  g_dinv[NMAX];
__device__ int2   g_csr[EMAX];          // {src, bitcast(dinv[src])}
__device__ float  g_Wt[D * D];          // W transposed: Wt[k][o]
__device__ float  g_coeff[KHOPS + 1];
__device__ int    g_is64;
__device__ int    g_bsum[BMAX];         // per-block degree partials

// ---------------- packed f32x2 helpers (Blackwell FFMA2 via PTX) -----------
__device__ __forceinline__ unsigned long long pack2(float v) {
    unsigned long long r;
    asm("mov.b64 %0, {%1, %1};" : "=l"(r) : "f"(v));
    return r;
}
__device__ __forceinline__ unsigned long long ffma2(
    unsigned long long a, unsigned long long b, unsigned long long c) {
    unsigned long long d;
    asm("fma.rn.f32x2 %0, %1, %2, %3;" : "=l"(d) : "l"(a), "l"(b), "l"(c));
    return d;
}
__device__ __forceinline__ float2 unpack2(unsigned long long v) {
    float lo, hi;
    asm("mov.b64 {%0, %1}, %2;" : "=f"(lo), "=f"(hi) : "l"(v));
    return make_float2(lo, hi);
}

// ---------------- fused setup: W transpose + dtype detect + coeffs ----------
__global__ void k_setup(const void* __restrict__ ei,
                        const float* __restrict__ t_ptr,
                        const float* __restrict__ W) {
    int i = blockIdx.x * blockDim.x + threadIdx.x;
    if (i < D * D) {
        int r = i / D, c = i % D;
        g_Wt[c * D + r] = W[r * D + c];
    }
    if (blockIdx.x == 0 && threadIdx.x == 0) {
        const int* a = (const int*)ei;
        int is64 = 1;
#pragma unroll
        for (int j = 1; j < 32; j += 2)
            if (a[j] != 0) is64 = 0;
        g_is64 = is64;
        float t = *t_ptr;
        float cc = expf(-t);
        g_coeff[0] = cc;
        for (int k = 1; k <= KHOPS; ++k) { cc = cc * t / (float)k; g_coeff[k] = cc; }
    }
}

__device__ __forceinline__ int load_idx(const void* ei, long long pos) {
    if (g_is64) return (int)((const long long*)ei)[pos];
    return ((const int*)ei)[pos];
}

__global__ void k_zero(int n) {
    int i = blockIdx.x * blockDim.x + threadIdx.x;
    if (i < n) g_deg[i] = 0;
}

__global__ void k_hist(const void* __restrict__ ei, int E) {
    int e = blockIdx.x * blockDim.x + threadIdx.x;
    if (e < E) {
        int dst = load_idx(ei, (long long)E + e);
        atomicAdd(&g_deg[dst], 1);
    }
}

// ---------------- 3-phase coalesced scan -------------------------------------
// Phase A: per-block degree sums (coalesced).
__global__ void __launch_bounds__(SCAN_T) k_blocksum(int n) {
    int i = blockIdx.x * SCAN_T + threadIdx.x;
    int v = (i < n) ? g_deg[i] : 0;
    int lane = threadIdx.x & 31, wid = threadIdx.x >> 5;
#pragma unroll
    for (int off = 16; off > 0; off >>= 1)
        v += __shfl_down_sync(0xffffffffu, v, off);
    __shared__ int ws[32];
    if (lane == 0) ws[wid] = v;
    __syncthreads();
    if (wid == 0) {
        int s = (lane < SCAN_T / 32) ? ws[lane] : 0;
#pragma unroll
        for (int off = 16; off > 0; off >>= 1)
            s += __shfl_down_sync(0xffffffffu, s, off);
        if (lane == 0) g_bsum[blockIdx.x] = s;
    }
}

// Phase B: exclusive scan of block partials (tiny).
__global__ void k_scanb(int nb) {
    int lane = threadIdx.x;
    int v = (lane < nb) ? g_bsum[lane] : 0;
    int orig = v;
#pragma unroll
    for (int off = 1; off < 64; off <<= 1) {
        int t = __shfl_up_sync(0xffffffffffffffffull & 0xffffffffu, v, off, 64);
        if ((lane & 63) >= off) v += t;
    }
    // blockDim 64: two warps; do it simply with shared memory instead
    __shared__ int s[BMAX];
    s[lane] = orig;
    __syncthreads();
    if (lane == 0) {
        int run = 0;
        for (int j = 0; j < nb; ++j) { int d = s[j]; s[j] = run; run += d; }
        s[nb] = run;  // total (nb < BMAX)
    }
    __syncthreads();
    g_bsum[lane] = s[lane];
}

// Phase C: intra-block exclusive scan + block offset; coalesced writes of
// rowptr, cursor, dinv.
__global__ void __launch_bounds__(SCAN_T) k_write(int n) {
    int i = blockIdx.x * SCAN_T + threadIdx.x;
    int d = (i < n) ? g_deg[i] : 0;
    int lane = threadIdx.x & 31, wid = threadIdx.x >> 5;

    int v = d;
#pragma unroll
    for (int off = 1; off < 32; off <<= 1) {
        int t = __shfl_up_sync(0xffffffffu, v, off);
        if (lane >= off) v += t;
    }
    __shared__ int ws[32];
    if (lane == 31) ws[wid] = v;
    __syncthreads();
    if (wid == 0) {
        int wv = ws[lane];
#pragma unroll
        for (int off = 1; off < 32; off <<= 1) {
            int t = __shfl_up_sync(0xffffffffu, wv, off);
            if (lane >= off) wv += t;
        }
        ws[lane] = wv;
    }
    __syncthreads();

    int excl = v - d + (wid ? ws[wid - 1] : 0) + g_bsum[blockIdx.x];
    if (i < n) {
        g_rowptr[i] = excl;
        g_cursor[i] = excl;
        g_dinv[i]   = rsqrtf((float)d + 1.0f);
        if (i == n - 1) g_rowptr[n] = excl + d;
    }
}

__global__ void k_scatter(const void* __restrict__ ei, int E) {
    int e = blockIdx.x * blockDim.x + threadIdx.x;
    if (e < E) {
        int src = load_idx(ei, e);
        int dst = load_idx(ei, (long long)E + e);
        int pos = atomicAdd(&g_cursor[dst], 1);
        g_csr[pos] = make_int2(src, __float_as_int(g_dinv[src]));
    }
}

// ------------- fp16 pack/unpack helpers -------------------------------------
__device__ __forceinline__ void fma_h4(uint2 p, float w, float4& a) {
    float2 lo = __half22float2(*(const __half2*)&p.x);
    float2 hi = __half22float2(*(const __half2*)&p.y);
    a.x = fmaf(w, lo.x, a.x); a.y = fmaf(w, lo.y, a.y);
    a.z = fmaf(w, hi.x, a.z); a.w = fmaf(w, hi.y, a.w);
}
__device__ __forceinline__ uint2 pack_h4(float4 r) {
    __half2 lo = __floats2half2_rn(r.x, r.y);
    __half2 hi = __floats2half2_rn(r.z, r.w);
    uint2 p;
    p.x = *(const unsigned int*)&lo;
    p.y = *(const unsigned int*)&hi;
    return p;
}

// ---------------- y = x @ W^T ; h0 = fp16(y) ; out = c0*y + b ---------------
// Packed-f32x2 GEMM: x tile staged in smem pre-duplicated as (x,x) u64s.
__global__ void __launch_bounds__(256) k_gemm_init(
    const float* __restrict__ x, const float* __restrict__ b,
    float* __restrict__ out, int n)
{
    __shared__ unsigned long long sdup[32 * D];   // 32 KB
    int tid  = threadIdx.x;
    int warp = tid >> 5;
    int lane = tid & 31;
    int rowb = blockIdx.x * 32;
    int rows = n - rowb; if (rows > 32) rows = 32;

    const float4* x4 = (const float4*)(x + (long long)rowb * D);
    for (int i = tid; i < rows * D4; i += 256) {
        float4 xv = x4[i];
        sdup[i * 4 + 0] = pack2(xv.x);
        sdup[i * 4 + 1] = pack2(xv.y);
        sdup[i * 4 + 2] = pack2(xv.z);
        sdup[i * 4 + 3] = pack2(xv.w);
    }
    __syncthreads();

    int r0 = warp * 4;
    if (rowb + r0 >= n) return;
    int nr = rows - r0; if (nr > 4) nr = 4;

    const ulonglong2* __restrict__ Wt2 = (const ulonglong2*)g_Wt;

    unsigned long long acc[4][2];
#pragma unroll
    for (int r = 0; r < 4; ++r) { acc[r][0] = 0ull; acc[r][1] = 0ull; }

#pragma unroll 4
    for (int kc = 0; kc < D; ++kc) {
        ulonglong2 wp = __ldg(&Wt2[kc * D4 + lane]);
        unsigned long long v0 = sdup[(r0 + 0) * D + kc];
        unsigned long long v1 = sdup[(r0 + 1) * D + kc];
        unsigned long long v2 = sdup[(r0 + 2) * D + kc];
        unsigned long long v3 = sdup[(r0 + 3) * D + kc];
        acc[0][0] = ffma2(v0, wp.x, acc[0][0]); acc[0][1] = ffma2(v0, wp.y, acc[0][1]);
        acc[1][0] = ffma2(v1, wp.x, acc[1][0]); acc[1][1] = ffma2(v1, wp.y, acc[1][1]);
        acc[2][0] = ffma2(v2, wp.x, acc[2][0]); acc[2][1] = ffma2(v2, wp.y, acc[2][1]);
        acc[3][0] = ffma2(v3, wp.x, acc[3][0]); acc[3][1] = ffma2(v3, wp.y, acc[3][1]);
    }

    float c0 = g_coeff[0];
    float4 b4 = __ldg(&((const float4*)b)[lane]);
    uint2*  h0 = (uint2*)g_bufA;
    float4* o4 = (float4*)out;

#pragma unroll
    for (int j = 0; j < 4; ++j) {
        if (j < nr) {
            int idx = (rowb + r0 + j) * D4 + lane;
            float2 lo = unpack2(acc[j][0]);
            float2 hi = unpack2(acc[j][1]);
            float4 r = make_float4(lo.x, lo.y, hi.x, hi.y);
            h0[idx] = pack_h4(r);
            float4 o;
            o.x = fmaf(c0, r.x, b4.x);
            o.y = fmaf(c0, r.y, b4.y);
            o.z = fmaf(c0, r.z, b4.z);
            o.w = fmaf(c0, r.w, b4.w);
            o4[idx] = o;
        }
    }
}

// ---------------- one diffusion hop (fp16 state) -----------------------------
__global__ void __launch_bounds__(256) k_hop(
    int flip, int k, int n, float4* __restrict__ out, int do_out, int write_h)
{
    int gw = (blockIdx.x * blockDim.x + threadIdx.x) >> 5;
    if (gw >= n) return;
    int lane = threadIdx.x & 31;

    const uint2* __restrict__ hin  = flip ? (const uint2*)g_bufB : (const uint2*)g_bufA;
    uint2*       __restrict__ hout = flip ? (uint2*)g_bufA       : (uint2*)g_bufB;

    int beg = g_rowptr[gw];
    int end = g_rowptr[gw + 1];

    uint2 ps = __ldg(&hin[gw * DH2 + lane]);

    float4 acc  = make_float4(0.f,0.f,0.f,0.f);
    float4 acc2 = make_float4(0.f,0.f,0.f,0.f);

    int e = beg;
    for (; e + 8 <= end; e += 8) {
        int2 c0 = __ldg(&g_csr[e + 0]);
        int2 c1 = __ldg(&g_csr[e + 1]);
        int2 c2 = __ldg(&g_csr[e + 2]);
        int2 c3 = __ldg(&g_csr[e + 3]);
        int2 c4 = __ldg(&g_csr[e + 4]);
        int2 c5 = __ldg(&g_csr[e + 5]);
        int2 c6 = __ldg(&g_csr[e + 6]);
        int2 c7 = __ldg(&g_csr[e + 7]);
        uint2 p0 = __ldg(&hin[c0.x * DH2 + lane]);
        uint2 p1 = __ldg(&hin[c1.x * DH2 + lane]);
        uint2 p2 = __ldg(&hin[c2.x * DH2 + lane]);
        uint2 p3 = __ldg(&hin[c3.x * DH2 + lane]);
        uint2 p4 = __ldg(&hin[c4.x * DH2 + lane]);
        uint2 p5 = __ldg(&hin[c5.x * DH2 + lane]);
        uint2 p6 = __ldg(&hin[c6.x * DH2 + lane]);
        uint2 p7 = __ldg(&hin[c7.x * DH2 + lane]);
        fma_h4(p0, __int_as_float(c0.y), acc);
        fma_h4(p1, __int_as_float(c1.y), acc2);
        fma_h4(p2, __int_as_float(c2.y), acc);
        fma_h4(p3, __int_as_float(c3.y), acc2);
        fma_h4(p4, __int_as_float(c4.y), acc);
        fma_h4(p5, __int_as_float(c5.y), acc2);
        fma_h4(p6, __int_as_float(c6.y), acc);
        fma_h4(p7, __int_as_float(c7.y), acc2);
    }
    for (; e + 4 <= end; e += 4) {
        int2 c0 = __ldg(&g_csr[e + 0]);
        int2 c1 = __ldg(&g_csr[e + 1]);
        int2 c2 = __ldg(&g_csr[e + 2]);
        int2 c3 = __ldg(&g_csr[e + 3]);
        uint2 p0 = __ldg(&hin[c0.x * DH2 + lane]);
        uint2 p1 = __ldg(&hin[c1.x * DH2 + lane]);
        uint2 p2 = __ldg(&hin[c2.x * DH2 + lane]);
        uint2 p3 = __ldg(&hin[c3.x * DH2 + lane]);
        fma_h4(p0, __int_as_float(c0.y), acc);
        fma_h4(p1, __int_as_float(c1.y), acc2);
        fma_h4(p2, __int_as_float(c2.y), acc);
        fma_h4(p3, __int_as_float(c3.y), acc2);
    }
    for (; e < end; ++e) {
        int2 c = __ldg(&g_csr[e]);
        uint2 p = __ldg(&hin[c.x * DH2 + lane]);
        fma_h4(p, __int_as_float(c.y), acc);
    }

    float di  = g_dinv[gw];
    float di2 = di * di;
    float2 slo = __half22float2(*(const __half2*)&ps.x);
    float2 shi = __half22float2(*(const __half2*)&ps.y);

    float4 r;
    r.x = fmaf(di, acc.x + acc2.x, di2 * slo.x);
    r.y = fmaf(di, acc.y + acc2.y, di2 * slo.y);
    r.z = fmaf(di, acc.z + acc2.z, di2 * shi.x);
    r.w = fmaf(di, acc.w + acc2.w, di2 * shi.y);

    int idx = gw * DH2 + lane;
    if (write_h) hout[idx] = pack_h4(r);

    if (do_out) {
        float cp = g_coeff[k - 1];
        float c  = g_coeff[k];
        float4 o = out[idx];
        o.x = fmaf(cp, slo.x, o.x);
        o.y = fmaf(cp, slo.y, o.y);
        o.z = fmaf(cp, shi.x, o.z);
        o.w = fmaf(cp, shi.y, o.w);
        o.x = fmaf(c, r.x, o.x);
        o.y = fmaf(c, r.y, o.y);
        o.z = fmaf(c, r.z, o.z);
        o.w = fmaf(c, r.w, o.w);
        out[idx] = o;
    }
}

// ---------------- launch ----------------------------------------------------
extern "C" void kernel_launch(void* const* d_in, const int* in_sizes, int n_in,
                              void* d_out, int out_size) {
    const float* x  = (const float*)d_in[0];
    const void*  ei = d_in[1];
    const float* t  = (const float*)d_in[2];
    const float* W  = (const float*)d_in[3];
    const float* b  = (const float*)d_in[4];
    float* out = (float*)d_out;

    int N = in_sizes[0] / D;
    int E = in_sizes[1] / 2;
    int nb = (N + SCAN_T - 1) / SCAN_T;

    k_setup<<<(D * D + 255) / 256, 256>>>(ei, t, W);
    k_zero<<<(N + 255) / 256, 256>>>(N);
    k_hist<<<(E + 255) / 256, 256>>>(ei, E);
    k_blocksum<<<nb, SCAN_T>>>(N);
    k_scanb<<<1, BMAX>>>(nb);
    k_write<<<nb, SCAN_T>>>(N);
    k_scatter<<<(E + 255) / 256, 256>>>(ei, E);
    k_gemm_init<<<(N + 31) / 32, 256>>>(x, b, out, N);

    int hop_blocks = (N + 7) / 8;   // 8 warps per block, warp per node
    for (int k = 1; k <= KHOPS; ++k) {
        int flip    = (k - 1) & 1;
        int do_out  = (k & 1) == 0;
        int write_h = (k < KHOPS);
        k_hop<<<hop_blocks, 256>>>(flip, k, N, (float4*)out, do_out, write_h);
    }
}

// round 9
// speedup vs baseline: 1.5131x; 1.1814x over previous
#include <cuda_runtime.h>
#include <cuda_fp16.h>

#define D      128
#define D4     32          // D/4 float4 per row (fp32 views)
#define DH2    32          // D/4 uint2 per row (fp16 views)
#define KHOPS  10
#define SCAN_T 1024
#define BM     32          // GEMM rows per block

static const int NMAX = 50000;
static const int EMAX = 625000;
static const int BMAX = 64;             // max scan blocks

// ---------------- scratch (device globals; no allocation allowed) ----------
__device__ __half g_bufA[NMAX * D];     // h ping (fp16 state)
__device__ __half g_bufB[NMAX * D];     // h pong
__device__ int    g_deg[NMAX];
__device__ int    g_rowptr[NMAX + 1];
__device__ int    g_cursor[NMAX];
__device__ float  g_dinv[NMAX];
__device__ int2   g_csr[EMAX];          // {src, bitcast(dinv[src])}
__device__ __half g_Wh[D * D];          // W in fp16, native [o][k] layout
__device__ float  g_coeff[KHOPS + 1];
__device__ int    g_is64;
__device__ int    g_bsum[BMAX];         // per-block degree partials

// ---------------- fused setup: W->fp16 + deg zero + detect + coeffs --------
__global__ void k_setup(const void* __restrict__ ei,
                        const float* __restrict__ t_ptr,
                        const float* __restrict__ W, int n) {
    int i = blockIdx.x * blockDim.x + threadIdx.x;
    if (i < D * D) g_Wh[i] = __float2half(W[i]);
    if (i < n)     g_deg[i] = 0;
    if (i == 0) {
        const int* a = (const int*)ei;
        int is64 = 1;
#pragma unroll
        for (int j = 1; j < 32; j += 2)
            if (a[j] != 0) is64 = 0;
        g_is64 = is64;
        float t = *t_ptr;
        float cc = expf(-t);
        g_coeff[0] = cc;
        for (int k = 1; k <= KHOPS; ++k) { cc = cc * t / (float)k; g_coeff[k] = cc; }
    }
}

__device__ __forceinline__ int load_idx(const void* ei, long long pos) {
    if (g_is64) return (int)((const long long*)ei)[pos];
    return ((const int*)ei)[pos];
}

__global__ void k_hist(const void* __restrict__ ei, int E) {
    int e = blockIdx.x * blockDim.x + threadIdx.x;
    if (e < E) {
        int dst = load_idx(ei, (long long)E + e);
        atomicAdd(&g_deg[dst], 1);
    }
}

// ---------------- 3-phase coalesced scan -------------------------------------
__global__ void __launch_bounds__(SCAN_T) k_blocksum(int n) {
    int i = blockIdx.x * SCAN_T + threadIdx.x;
    int v = (i < n) ? g_deg[i] : 0;
    int lane = threadIdx.x & 31, wid = threadIdx.x >> 5;
#pragma unroll
    for (int off = 16; off > 0; off >>= 1)
        v += __shfl_down_sync(0xffffffffu, v, off);
    __shared__ int ws[32];
    if (lane == 0) ws[wid] = v;
    __syncthreads();
    if (wid == 0) {
        int s = (lane < SCAN_T / 32) ? ws[lane] : 0;
#pragma unroll
        for (int off = 16; off > 0; off >>= 1)
            s += __shfl_down_sync(0xffffffffu, s, off);
        if (lane == 0) g_bsum[blockIdx.x] = s;
    }
}

__global__ void k_scanb(int nb) {
    int lane = threadIdx.x;
    __shared__ int s[BMAX];
    s[lane] = (lane < nb) ? g_bsum[lane] : 0;
    __syncthreads();
    if (lane == 0) {
        int run = 0;
        for (int j = 0; j < nb; ++j) { int d = s[j]; s[j] = run; run += d; }
    }
    __syncthreads();
    g_bsum[lane] = s[lane];
}

__global__ void __launch_bounds__(SCAN_T) k_write(int n) {
    int i = blockIdx.x * SCAN_T + threadIdx.x;
    int d = (i < n) ? g_deg[i] : 0;
    int lane = threadIdx.x & 31, wid = threadIdx.x >> 5;

    int v = d;
#pragma unroll
    for (int off = 1; off < 32; off <<= 1) {
        int t = __shfl_up_sync(0xffffffffu, v, off);
        if (lane >= off) v += t;
    }
    __shared__ int ws[32];
    if (lane == 31) ws[wid] = v;
    __syncthreads();
    if (wid == 0) {
        int wv = ws[lane];
#pragma unroll
        for (int off = 1; off < 32; off <<= 1) {
            int t = __shfl_up_sync(0xffffffffu, wv, off);
            if (lane >= off) wv += t;
        }
        ws[lane] = wv;
    }
    __syncthreads();

    int excl = v - d + (wid ? ws[wid - 1] : 0) + g_bsum[blockIdx.x];
    if (i < n) {
        g_rowptr[i] = excl;
        g_cursor[i] = excl;
        g_dinv[i]   = rsqrtf((float)d + 1.0f);
        if (i == n - 1) g_rowptr[n] = excl + d;
    }
}

__global__ void k_scatter(const void* __restrict__ ei, int E) {
    int e = blockIdx.x * blockDim.x + threadIdx.x;
    if (e < E) {
        int src = load_idx(ei, e);
        int dst = load_idx(ei, (long long)E + e);
        int pos = atomicAdd(&g_cursor[dst], 1);
        g_csr[pos] = make_int2(src, __float_as_int(g_dinv[src]));
    }
}

// ------------- fp16 pack/unpack helpers -------------------------------------
__device__ __forceinline__ void fma_h4(uint2 p, float w, float4& a) {
    float2 lo = __half22float2(*(const __half2*)&p.x);
    float2 hi = __half22float2(*(const __half2*)&p.y);
    a.x = fmaf(w, lo.x, a.x); a.y = fmaf(w, lo.y, a.y);
    a.z = fmaf(w, hi.x, a.z); a.w = fmaf(w, hi.y, a.w);
}
__device__ __forceinline__ uint2 pack_h4(float4 r) {
    __half2 lo = __floats2half2_rn(r.x, r.y);
    __half2 hi = __floats2half2_rn(r.z, r.w);
    uint2 p;
    p.x = *(const unsigned int*)&lo;
    p.y = *(const unsigned int*)&hi;
    return p;
}

__device__ __forceinline__ unsigned int smem_u32(const void* p) {
    return (unsigned int)__cvta_generic_to_shared(p);
}

// ---------------- HMMA GEMM: y = x @ W^T ; h0 = fp16(y) ; out = c0*y + b ----
// Block: 256 threads (8 warps), 32 rows x 128 cols of output.
// A = x rows (fp16 in smem), B = W[o][k] fp16 in smem.
// B fragment: storage [n][k] is already "col-major" for the kxn view ->
// NON-trans ldmatrix with rows addressed by n gives the exact fragment.
__global__ void __launch_bounds__(256) k_gemm_mma(
    const float* __restrict__ x, const float* __restrict__ b,
    float* __restrict__ out, int n)
{
    __shared__ __align__(16) __half sA[BM][D + 8];      // 32 x 136
    __shared__ __align__(16) __half sW[D][D + 8];       // 128 x 136

    int tid  = threadIdx.x;
    int warp = tid >> 5;
    int lane = tid & 31;
    int rowb = blockIdx.x * BM;
    int rows = n - rowb; if (rows > BM) rows = BM;

    // load W tile (fp16, 128x128) -- 2048 uint4, 8 per thread
    const uint4* Wh4 = (const uint4*)g_Wh;
#pragma unroll
    for (int i = tid; i < D * (D / 8); i += 256) {
        int r = i >> 4, c = i & 15;
        *(uint4*)&sW[r][c * 8] = __ldg(&Wh4[r * 16 + c]);
    }
    // load + convert x rows (fp32 -> fp16)
    const float4* x4 = (const float4*)(x + (long long)rowb * D);
    for (int i = tid; i < rows * D4; i += 256) {
        int r = i >> 5, c = i & 31;
        float4 v = x4[i];
        *(half2*)&sA[r][c * 4]     = __floats2half2_rn(v.x, v.y);
        *(half2*)&sA[r][c * 4 + 2] = __floats2half2_rn(v.z, v.w);
    }
    __syncthreads();

    int rg = warp & 1;           // 0..1 : rows rg*16
    int cg = warp >> 1;          // 0..3 : cols cg*32
    int r0 = rg * 16;

    float acc[4][4];
#pragma unroll
    for (int j = 0; j < 4; ++j)
#pragma unroll
        for (int q = 0; q < 4; ++q) acc[j][q] = 0.f;

    // ldmatrix lane addressing
    int aRow = r0 + (lane & 15);
    int aCol = (lane >> 4) << 3;
    // B (non-trans): lanes 0-7 -> (n, k0); 8-15 -> (n, k0+8);
    //                lanes 16-23 -> (n+8, k0); 24-31 -> (n+8, k0+8)
    int bN = (lane & 7) + ((lane >> 4) << 3);
    int bK = ((lane >> 3) & 1) << 3;

#pragma unroll
    for (int k0 = 0; k0 < D; k0 += 16) {
        unsigned int a0, a1, a2, a3;
        unsigned int aAddr = smem_u32(&sA[aRow][k0 + aCol]);
        asm volatile("ldmatrix.sync.aligned.m8n8.x4.shared.b16 {%0,%1,%2,%3}, [%4];"
                     : "=r"(a0), "=r"(a1), "=r"(a2), "=r"(a3) : "r"(aAddr));

#pragma unroll
        for (int half16 = 0; half16 < 2; ++half16) {
            int nbase = cg * 32 + half16 * 16;
            unsigned int b0, b1, b2, b3;
            unsigned int bAddr = smem_u32(&sW[nbase + bN][k0 + bK]);
            asm volatile("ldmatrix.sync.aligned.m8n8.x4.shared.b16 {%0,%1,%2,%3}, [%4];"
                         : "=r"(b0), "=r"(b1), "=r"(b2), "=r"(b3) : "r"(bAddr));
            int j0 = half16 * 2;
            asm volatile("mma.sync.aligned.m16n8k16.row.col.f32.f16.f16.f32 "
                         "{%0,%1,%2,%3},{%4,%5,%6,%7},{%8,%9},{%0,%1,%2,%3};"
                         : "+f"(acc[j0][0]), "+f"(acc[j0][1]), "+f"(acc[j0][2]), "+f"(acc[j0][3])
                         : "r"(a0), "r"(a1), "r"(a2), "r"(a3), "r"(b0), "r"(b1));
            asm volatile("mma.sync.aligned.m16n8k16.row.col.f32.f16.f16.f32 "
                         "{%0,%1,%2,%3},{%4,%5,%6,%7},{%8,%9},{%0,%1,%2,%3};"
                         : "+f"(acc[j0+1][0]), "+f"(acc[j0+1][1]), "+f"(acc[j0+1][2]), "+f"(acc[j0+1][3])
                         : "r"(a0), "r"(a1), "r"(a2), "r"(a3), "r"(b2), "r"(b3));
        }
    }

    // epilogue: out = c0*acc + b (fp32), h0 = fp16(acc)
    float c0 = g_coeff[0];
    int mlo = rowb + r0 + (lane >> 2);
    int mhi = mlo + 8;
    __half2* h0 = (__half2*)g_bufA;

#pragma unroll
    for (int j = 0; j < 4; ++j) {
        int col = cg * 32 + j * 8 + ((lane & 3) << 1);
        float2 bb = __ldg((const float2*)(b + col));
        if (mlo < n) {
            long long idx = (long long)mlo * D + col;
            *(float2*)(out + idx) = make_float2(fmaf(c0, acc[j][0], bb.x),
                                                fmaf(c0, acc[j][1], bb.y));
            h0[idx >> 1] = __floats2half2_rn(acc[j][0], acc[j][1]);
        }
        if (mhi < n) {
            long long idx = (long long)mhi * D + col;
            *(float2*)(out + idx) = make_float2(fmaf(c0, acc[j][2], bb.x),
                                                fmaf(c0, acc[j][3], bb.y));
            h0[idx >> 1] = __floats2half2_rn(acc[j][2], acc[j][3]);
        }
    }
}

// ---------------- one diffusion hop (fp16 state) -----------------------------
__global__ void __launch_bounds__(256) k_hop(
    int flip, int k, int n, float4* __restrict__ out, int do_out, int write_h)
{
    int gw = (blockIdx.x * blockDim.x + threadIdx.x) >> 5;
    if (gw >= n) return;
    int lane = threadIdx.x & 31;

    const uint2* __restrict__ hin  = flip ? (const uint2*)g_bufB : (const uint2*)g_bufA;
    uint2*       __restrict__ hout = flip ? (uint2*)g_bufA       : (uint2*)g_bufB;

    int beg = g_rowptr[gw];
    int end = g_rowptr[gw + 1];

    uint2 ps = __ldg(&hin[gw * DH2 + lane]);

    float4 acc  = make_float4(0.f,0.f,0.f,0.f);
    float4 acc2 = make_float4(0.f,0.f,0.f,0.f);

    int e = beg;
    for (; e + 8 <= end; e += 8) {
        int2 c0 = __ldg(&g_csr[e + 0]);
        int2 c1 = __ldg(&g_csr[e + 1]);
        int2 c2 = __ldg(&g_csr[e + 2]);
        int2 c3 = __ldg(&g_csr[e + 3]);
        int2 c4 = __ldg(&g_csr[e + 4]);
        int2 c5 = __ldg(&g_csr[e + 5]);
        int2 c6 = __ldg(&g_csr[e + 6]);
        int2 c7 = __ldg(&g_csr[e + 7]);
        uint2 p0 = __ldg(&hin[c0.x * DH2 + lane]);
        uint2 p1 = __ldg(&hin[c1.x * DH2 + lane]);
        uint2 p2 = __ldg(&hin[c2.x * DH2 + lane]);
        uint2 p3 = __ldg(&hin[c3.x * DH2 + lane]);
        uint2 p4 = __ldg(&hin[c4.x * DH2 + lane]);
        uint2 p5 = __ldg(&hin[c5.x * DH2 + lane]);
        uint2 p6 = __ldg(&hin[c6.x * DH2 + lane]);
        uint2 p7 = __ldg(&hin[c7.x * DH2 + lane]);
        fma_h4(p0, __int_as_float(c0.y), acc);
        fma_h4(p1, __int_as_float(c1.y), acc2);
        fma_h4(p2, __int_as_float(c2.y), acc);
        fma_h4(p3, __int_as_float(c3.y), acc2);
        fma_h4(p4, __int_as_float(c4.y), acc);
        fma_h4(p5, __int_as_float(c5.y), acc2);
        fma_h4(p6, __int_as_float(c6.y), acc);
        fma_h4(p7, __int_as_float(c7.y), acc2);
    }
    for (; e + 4 <= end; e += 4) {
        int2 c0 = __ldg(&g_csr[e + 0]);
        int2 c1 = __ldg(&g_csr[e + 1]);
        int2 c2 = __ldg(&g_csr[e + 2]);
        int2 c3 = __ldg(&g_csr[e + 3]);
        uint2 p0 = __ldg(&hin[c0.x * DH2 + lane]);
        uint2 p1 = __ldg(&hin[c1.x * DH2 + lane]);
        uint2 p2 = __ldg(&hin[c2.x * DH2 + lane]);
        uint2 p3 = __ldg(&hin[c3.x * DH2 + lane]);
        fma_h4(p0, __int_as_float(c0.y), acc);
        fma_h4(p1, __int_as_float(c1.y), acc2);
        fma_h4(p2, __int_as_float(c2.y), acc);
        fma_h4(p3, __int_as_float(c3.y), acc2);
    }
    for (; e < end; ++e) {
        int2 c = __ldg(&g_csr[e]);
        uint2 p = __ldg(&hin[c.x * DH2 + lane]);
        fma_h4(p, __int_as_float(c.y), acc);
    }

    float di  = g_dinv[gw];
    float di2 = di * di;
    float2 slo = __half22float2(*(const __half2*)&ps.x);
    float2 shi = __half22float2(*(const __half2*)&ps.y);

    float4 r;
    r.x = fmaf(di, acc.x + acc2.x, di2 * slo.x);
    r.y = fmaf(di, acc.y + acc2.y, di2 * slo.y);
    r.z = fmaf(di, acc.z + acc2.z, di2 * shi.x);
    r.w = fmaf(di, acc.w + acc2.w, di2 * shi.y);

    int idx = gw * DH2 + lane;
    if (write_h) hout[idx] = pack_h4(r);

    if (do_out) {
        float cp = g_coeff[k - 1];
        float c  = g_coeff[k];
        float4 o = out[idx];
        o.x = fmaf(cp, slo.x, o.x);
        o.y = fmaf(cp, slo.y, o.y);
        o.z = fmaf(cp, shi.x, o.z);
        o.w = fmaf(cp, shi.y, o.w);
        o.x = fmaf(c, r.x, o.x);
        o.y = fmaf(c, r.y, o.y);
        o.z = fmaf(c, r.z, o.z);
        o.w = fmaf(c, r.w, o.w);
        out[idx] = o;
    }
}

// ---------------- launch ----------------------------------------------------
extern "C" void kernel_launch(void* const* d_in, const int* in_sizes, int n_in,
                              void* d_out, int out_size) {
    const float* x  = (const float*)d_in[0];
    const void*  ei = d_in[1];
    const float* t  = (const float*)d_in[2];
    const float* W  = (const float*)d_in[3];
    const float* b  = (const float*)d_in[4];
    float* out = (float*)d_out;

    int N = in_sizes[0] / D;
    int E = in_sizes[1] / 2;
    int nb = (N + SCAN_T - 1) / SCAN_T;
    int setup_elems = (N > D * D) ? N : D * D;

    k_setup<<<(setup_elems + 255) / 256, 256>>>(ei, t, W, N);
    k_hist<<<(E + 255) / 256, 256>>>(ei, E);
    k_blocksum<<<nb, SCAN_T>>>(N);
    k_scanb<<<1, BMAX>>>(nb);
    k_write<<<nb, SCAN_T>>>(N);
    k_scatter<<<(E + 255) / 256, 256>>>(ei, E);
    k_gemm_mma<<<(N + BM - 1) / BM, 256>>>(x, b, out, N);

    int hop_blocks = (N + 7) / 8;   // 8 warps per block, warp per node
    for (int k = 1; k <= KHOPS; ++k) {
        int flip    = (k - 1) & 1;
        int do_out  = (k & 1) == 0;
        int write_h = (k < KHOPS);
        k_hop<<<hop_blocks, 256>>>(flip, k, N, (float4*)out, do_out, write_h);
    }
}